// round 1
// baseline (speedup 1.0000x reference)
#include <cuda_runtime.h>
#include <math.h>

// Problem constants
#define BATCH 8
#define NC    16
#define HH    320
#define WW    320
#define HW    102400          // 320*320
#define NITER 10
#define RED_BLKS 400          // blocks per batch in elementwise kernels (102400/256)

// ---------------- scratch (device globals; no runtime allocation) ----------------
__device__ float2 g_k[BATCH * NC * HW];   // coil k-space / image buffer (~105 MB)
__device__ float2 g_x[BATCH * HW];
__device__ float2 g_r[BATCH * HW];
__device__ float2 g_p[BATCH * HW];
__device__ float2 g_Ap[BATCH * HW];
__device__ float  g_part[BATCH * RED_BLKS];
__device__ float  g_rTr[BATCH];
__device__ float  g_alpha[BATCH];
__device__ float  g_beta[BATCH];

// ---------------- complex helpers ----------------
__device__ __forceinline__ float2 cmul(float2 a, float2 b) {
    return make_float2(a.x*b.x - a.y*b.y, a.x*b.y + a.y*b.x);
}
__device__ __forceinline__ float2 cmulconj(float2 c, float2 v) { // conj(c)*v
    return make_float2(c.x*v.x + c.y*v.y, c.x*v.y - c.y*v.x);
}
__device__ __forceinline__ float2 cadd(float2 a, float2 b) { return make_float2(a.x+b.x, a.y+b.y); }
__device__ __forceinline__ float2 csub(float2 a, float2 b) { return make_float2(a.x-b.x, a.y-b.y); }

// ---------------- 320-point FFT, one warp per line, DIF Stockham ----------------
// factors 5,4,4,4 ; in/out natural order; input in A, output ends in A.
// DIR = -1 forward (exp(-i...)), +1 inverse-unnormalized (exp(+i...)).
#define C51 0.30901699437494745f
#define C52 (-0.8090169943749475f)
#define S51 0.9510565162951535f
#define S52 0.5877852522924731f
#define TWOPI 6.283185307179586f

template<int DIR>
__device__ __forceinline__ void fft320_warp(float2* A, float2* B, int lane) {
    const float dir = (float)DIR;

    // stage 0: n=320, s=1, r=5, m=64  (64 butterflies)
    #pragma unroll
    for (int ii = 0; ii < 2; ii++) {
        int p = lane + 32 * ii;
        float2 a0 = A[p], a1 = A[p+64], a2 = A[p+128], a3 = A[p+192], a4 = A[p+256];
        float2 t1 = cadd(a1, a4), t2 = cadd(a2, a3);
        float2 t3 = csub(a1, a4), t4 = csub(a2, a3);
        float2 m1 = make_float2(a0.x + C51*t1.x + C52*t2.x, a0.y + C51*t1.y + C52*t2.y);
        float2 m2 = make_float2(a0.x + C52*t1.x + C51*t2.x, a0.y + C52*t1.y + C51*t2.y);
        float2 u1 = make_float2(S51*t3.x + S52*t4.x, S51*t3.y + S52*t4.y);
        float2 u2 = make_float2(S52*t3.x - S51*t4.x, S52*t3.y - S51*t4.y);
        float2 b0 = make_float2(a0.x + t1.x + t2.x, a0.y + t1.y + t2.y);
        float2 b1 = make_float2(m1.x - dir*u1.y, m1.y + dir*u1.x);
        float2 b4 = make_float2(m1.x + dir*u1.y, m1.y - dir*u1.x);
        float2 b2 = make_float2(m2.x - dir*u2.y, m2.y + dir*u2.x);
        float2 b3 = make_float2(m2.x + dir*u2.y, m2.y - dir*u2.x);
        float sn, cs;
        sincosf(dir * (TWOPI / 320.f) * (float)p, &sn, &cs);
        float2 w1 = make_float2(cs, sn);
        float2 w2 = cmul(w1, w1);
        float2 w3 = cmul(w2, w1);
        float2 w4 = cmul(w2, w2);
        int o = 5 * p;
        B[o]   = b0;
        B[o+1] = cmul(b1, w1);
        B[o+2] = cmul(b2, w2);
        B[o+3] = cmul(b3, w3);
        B[o+4] = cmul(b4, w4);
    }
    __syncwarp();

    // radix-4 butterfly macro
#define RAD4(a0,a1,a2,a3,b0o,b1o,b2o,b3o) {                              \
        float2 t0 = cadd(a0, a2), u1 = csub(a0, a2);                     \
        float2 t2 = cadd(a1, a3), u3 = csub(a1, a3);                     \
        b0o = cadd(t0, t2);                                              \
        b2o = csub(t0, t2);                                              \
        b1o = make_float2(u1.x - dir*u3.y, u1.y + dir*u3.x);             \
        b3o = make_float2(u1.x + dir*u3.y, u1.y - dir*u3.x); }

    // stage 1: n=64, s=5, r=4, m=16  (80 butterflies)
    for (int i = lane; i < 80; i += 32) {
        int q = i % 5, p = i / 5;
        float2 a0 = B[i], a1 = B[i+80], a2 = B[i+160], a3 = B[i+240];
        float2 b0, b1, b2, b3;
        RAD4(a0, a1, a2, a3, b0, b1, b2, b3);
        float sn, cs;
        sincosf(dir * (TWOPI / 64.f) * (float)p, &sn, &cs);
        float2 w1 = make_float2(cs, sn);
        float2 w2 = cmul(w1, w1);
        float2 w3 = cmul(w2, w1);
        int o = q + 20 * p;
        A[o]    = b0;
        A[o+5]  = cmul(b1, w1);
        A[o+10] = cmul(b2, w2);
        A[o+15] = cmul(b3, w3);
    }
    __syncwarp();

    // stage 2: n=16, s=20, r=4, m=4  (80 butterflies)
    for (int i = lane; i < 80; i += 32) {
        int q = i % 20, p = i / 20;
        float2 a0 = A[i], a1 = A[i+80], a2 = A[i+160], a3 = A[i+240];
        float2 b0, b1, b2, b3;
        RAD4(a0, a1, a2, a3, b0, b1, b2, b3);
        float sn, cs;
        sincosf(dir * (TWOPI / 16.f) * (float)p, &sn, &cs);
        float2 w1 = make_float2(cs, sn);
        float2 w2 = cmul(w1, w1);
        float2 w3 = cmul(w2, w1);
        int o = q + 80 * p;
        B[o]    = b0;
        B[o+20] = cmul(b1, w1);
        B[o+40] = cmul(b2, w2);
        B[o+60] = cmul(b3, w3);
    }
    __syncwarp();

    // stage 3: n=4, s=80, r=4, m=1  (80 butterflies, no twiddle)
    for (int i = lane; i < 80; i += 32) {
        float2 a0 = B[i], a1 = B[i+80], a2 = B[i+160], a3 = B[i+240];
        float2 b0, b1, b2, b3;
        RAD4(a0, a1, a2, a3, b0, b1, b2, b3);
        A[i]     = b0;
        A[i+80]  = b1;
        A[i+160] = b2;
        A[i+240] = b3;
    }
    __syncwarp();
#undef RAD4
}

// ---------------- block reduction helper (deterministic tree) ----------------
__device__ __forceinline__ float block_reduce_256(float v) {
    __shared__ float red[256];
    red[threadIdx.x] = v;
    __syncthreads();
    #pragma unroll
    for (int s = 128; s > 0; s >>= 1) {
        if (threadIdx.x < s) red[threadIdx.x] += red[threadIdx.x + s];
        __syncthreads();
    }
    return red[0];
}

// ---------------- K1: coil = csm*p ; forward FFT along W ----------------
__global__ void __launch_bounds__(256) k_rows_fwd(const float* __restrict__ csm) {
    __shared__ float2 sA[8][320];
    __shared__ float2 sB[8][320];
    int warp = threadIdx.x >> 5, lane = threadIdx.x & 31;
    int row = blockIdx.x * 8 + warp;          // [0, 128*320)
    int bc = row / 320, h = row % 320;
    int b = bc >> 4;
    const float2* csm2 = (const float2*)csm;
    const float2* prow = g_p + b * HW + h * WW;
    const float2* crow = csm2 + bc * HW + h * WW;
    for (int j = lane; j < WW; j += 32) sA[warp][j] = cmul(crow[j], prow[j]);
    __syncwarp();
    fft320_warp<-1>(sA[warp], sB[warp], lane);
    float2* out = g_k + bc * HW + h * WW;
    for (int j = lane; j < WW; j += 32) out[j] = sA[warp][j];
}

// ---------------- K2: column FFT, mask, column IFFT (scale folded here) ----------------
__global__ void __launch_bounds__(256) k_cols(const int* __restrict__ mask) {
    __shared__ float2 sA[8][321];
    __shared__ float2 sB[8][321];
    int bc = blockIdx.x / 40;
    int w0 = (blockIdx.x % 40) * 8;
    int b = bc >> 4;
    float2* base = g_k + bc * HW;
    // coalesced cooperative load: 8 adjacent columns
    for (int idx = threadIdx.x; idx < 320 * 8; idx += 256) {
        int h = idx >> 3, c = idx & 7;
        sA[c][h] = base[h * WW + w0 + c];
    }
    __syncthreads();
    int warp = threadIdx.x >> 5, lane = threadIdx.x & 31;
    fft320_warp<-1>(sA[warp], sB[warp], lane);
    const int* mcol = mask + b * HW + w0 + warp;
    for (int h = lane; h < 320; h += 32) {
        float m = (float)mcol[h * WW] * (1.0f / 102400.0f);   // ortho^2 scale
        sA[warp][h].x *= m;
        sA[warp][h].y *= m;
    }
    __syncwarp();
    fft320_warp<1>(sA[warp], sB[warp], lane);
    __syncthreads();
    for (int idx = threadIdx.x; idx < 320 * 8; idx += 256) {
        int h = idx >> 3, c = idx & 7;
        base[h * WW + w0 + c] = sA[c][h];
    }
}

// ---------------- K3: inverse FFT along W ; multiply conj(csm) ----------------
__global__ void __launch_bounds__(256) k_rows_inv(const float* __restrict__ csm) {
    __shared__ float2 sA[8][320];
    __shared__ float2 sB[8][320];
    int warp = threadIdx.x >> 5, lane = threadIdx.x & 31;
    int row = blockIdx.x * 8 + warp;
    int bc = row / 320, h = row % 320;
    const float2* csm2 = (const float2*)csm;
    float2* krow = g_k + bc * HW + h * WW;
    const float2* crow = csm2 + bc * HW + h * WW;
    for (int j = lane; j < WW; j += 32) sA[warp][j] = krow[j];
    __syncwarp();
    fft320_warp<1>(sA[warp], sB[warp], lane);
    for (int j = lane; j < WW; j += 32) krow[j] = cmulconj(crow[j], sA[warp][j]);
}

// ---------------- K4: Ap = sum_c coilimg + lam*p ; partial p.Ap ----------------
__global__ void __launch_bounds__(256) k_combine(const float* __restrict__ lam) {
    int b = blockIdx.x / RED_BLKS;
    int idx = (blockIdx.x % RED_BLKS) * 256 + threadIdx.x;
    int e = b * HW + idx;
    float2 s = make_float2(0.f, 0.f);
    #pragma unroll
    for (int c = 0; c < NC; c++) {
        float2 v = g_k[(b * NC + c) * HW + idx];
        s.x += v.x; s.y += v.y;
    }
    float2 pv = g_p[e];
    float l = lam[0];
    float2 ap = make_float2(s.x + l * pv.x, s.y + l * pv.y);
    g_Ap[e] = ap;
    float pd = pv.x * ap.x + pv.y * ap.y;   // Re(conj(p)*Ap)
    float tot = block_reduce_256(pd);
    if (threadIdx.x == 0) g_part[blockIdx.x] = tot;
}

// ---------------- K4b: alpha = rTr / pAp ----------------
__global__ void __launch_bounds__(256) k_alpha() {
    int b = blockIdx.x;
    float v = 0.f;
    for (int t = threadIdx.x; t < RED_BLKS; t += 256) v += g_part[b * RED_BLKS + t];
    float tot = block_reduce_256(v);
    if (threadIdx.x == 0) g_alpha[b] = g_rTr[b] / tot;
}

// ---------------- K5: x += a p ; r -= a Ap ; partial rTr_new ----------------
__global__ void __launch_bounds__(256) k_update_xr() {
    int b = blockIdx.x / RED_BLKS;
    int idx = (blockIdx.x % RED_BLKS) * 256 + threadIdx.x;
    int e = b * HW + idx;
    float a = g_alpha[b];
    float2 pv = g_p[e], ap = g_Ap[e];
    float2 xv = g_x[e];
    xv.x += a * pv.x; xv.y += a * pv.y;
    g_x[e] = xv;
    float2 rv = g_r[e];
    rv.x -= a * ap.x; rv.y -= a * ap.y;
    g_r[e] = rv;
    float rr = rv.x * rv.x + rv.y * rv.y;
    float tot = block_reduce_256(rr);
    if (threadIdx.x == 0) g_part[blockIdx.x] = tot;
}

// ---------------- K5b: beta = rTr_new / rTr ; rTr = rTr_new ----------------
__global__ void __launch_bounds__(256) k_beta() {
    int b = blockIdx.x;
    float v = 0.f;
    for (int t = threadIdx.x; t < RED_BLKS; t += 256) v += g_part[b * RED_BLKS + t];
    float tot = block_reduce_256(v);
    if (threadIdx.x == 0) {
        g_beta[b] = tot / g_rTr[b];
        g_rTr[b] = tot;
    }
}

// ---------------- K6: p = r + beta p ----------------
__global__ void __launch_bounds__(256) k_update_p() {
    int b = blockIdx.x / RED_BLKS;
    int idx = (blockIdx.x % RED_BLKS) * 256 + threadIdx.x;
    int e = b * HW + idx;
    float be = g_beta[b];
    float2 rv = g_r[e], pv = g_p[e];
    g_p[e] = make_float2(rv.x + be * pv.x, rv.y + be * pv.y);
}

// ---------------- init: p=r=rhs (complex), x=0, partial rTr ----------------
__global__ void __launch_bounds__(256) k_init(const float* __restrict__ rhs) {
    int b = blockIdx.x / RED_BLKS;
    int idx = (blockIdx.x % RED_BLKS) * 256 + threadIdx.x;
    int e = b * HW + idx;
    float re = rhs[(b * 2 + 0) * HW + idx];
    float im = rhs[(b * 2 + 1) * HW + idx];
    float2 v = make_float2(re, im);
    g_p[e] = v;
    g_r[e] = v;
    g_x[e] = make_float2(0.f, 0.f);
    float rr = re * re + im * im;
    float tot = block_reduce_256(rr);
    if (threadIdx.x == 0) g_part[blockIdx.x] = tot;
}

__global__ void __launch_bounds__(256) k_init_red() {
    int b = blockIdx.x;
    float v = 0.f;
    for (int t = threadIdx.x; t < RED_BLKS; t += 256) v += g_part[b * RED_BLKS + t];
    float tot = block_reduce_256(v);
    if (threadIdx.x == 0) g_rTr[b] = tot;
}

// ---------------- output: [B,H,W,2] ----------------
__global__ void __launch_bounds__(256) k_out(float* __restrict__ out) {
    int e = blockIdx.x * 256 + threadIdx.x;   // [0, 819200)
    float2 v = g_x[e];
    out[2 * e]     = v.x;
    out[2 * e + 1] = v.y;
}

// ---------------- launch ----------------
extern "C" void kernel_launch(void* const* d_in, const int* in_sizes, int n_in,
                              void* d_out, int out_size) {
    const float* rhs  = (const float*)d_in[0];
    const float* csm  = (const float*)d_in[1];
    const int*   mask = (const int*)d_in[2];
    const float* lam  = (const float*)d_in[3];
    float* out = (float*)d_out;

    const int EG = BATCH * RED_BLKS;   // 3200 blocks for elementwise kernels
    const int FG = BATCH * NC * HH / 8; // 5120 blocks for FFT kernels

    k_init<<<EG, 256>>>(rhs);
    k_init_red<<<BATCH, 256>>>();

    for (int it = 0; it < NITER; it++) {
        k_rows_fwd<<<FG, 256>>>(csm);
        k_cols<<<FG, 256>>>(mask);
        k_rows_inv<<<FG, 256>>>(csm);
        k_combine<<<EG, 256>>>(lam);
        k_alpha<<<BATCH, 256>>>();
        k_update_xr<<<EG, 256>>>();
        k_beta<<<BATCH, 256>>>();
        k_update_p<<<EG, 256>>>();
    }

    k_out<<<EG, 256>>>(out);
}

// round 2
// speedup vs baseline: 1.4816x; 1.4816x over previous
#include <cuda_runtime.h>
#include <math.h>

// Problem constants
#define BATCH 8
#define NC    16
#define HH    320
#define WW    320
#define HW    102400          // 320*320
#define NITER 10
#define RED_BLKS 400          // blocks per batch in elementwise kernels (102400/256)
#define TWOPI 6.283185307179586f
#define PI_F  3.14159265358979323846f

// ---------------- scratch (device globals; no runtime allocation) ----------------
__device__ float2 g_k[BATCH * NC * HW];   // coil k-space buffer (permuted freq layout)
__device__ float2 g_x[BATCH * HW];
__device__ float2 g_r[BATCH * HW];
__device__ float2 g_p[BATCH * HW];
__device__ float2 g_Ap[BATCH * HW];
__device__ float  g_maskP[BATCH * HW];    // permuted + scaled mask
__device__ float  g_part[BATCH * RED_BLKS];
__device__ float  g_rTr[BATCH];
__device__ float  g_alpha[BATCH];
__device__ float  g_beta[BATCH];

// ---------------- complex helpers ----------------
__device__ __forceinline__ float2 cmul(float2 a, float2 b) {
    return make_float2(a.x*b.x - a.y*b.y, a.x*b.y + a.y*b.x);
}
__device__ __forceinline__ float2 cmulconj(float2 c, float2 v) { // conj(c)*v
    return make_float2(c.x*v.x + c.y*v.y, c.x*v.y - c.y*v.x);
}
__device__ __forceinline__ float2 cadd(float2 a, float2 b) { return make_float2(a.x+b.x, a.y+b.y); }
__device__ __forceinline__ float2 csub(float2 a, float2 b) { return make_float2(a.x-b.x, a.y-b.y); }

__device__ __forceinline__ int br5(int l) { return (int)(__brev((unsigned)l) >> 27); }

// ---------------- radix-5 (verified round 1) ----------------
#define C51 0.30901699437494745f
#define C52 (-0.8090169943749475f)
#define S51 0.9510565162951535f
#define S52 0.5877852522924731f

template<int DIR>
__device__ __forceinline__ void fft5(float2 a0, float2 a1, float2 a2, float2 a3, float2 a4,
                                     float2& b0, float2& b1, float2& b2, float2& b3, float2& b4) {
    const float dir = (float)DIR;
    float2 t1 = cadd(a1, a4), t2 = cadd(a2, a3);
    float2 t3 = csub(a1, a4), t4 = csub(a2, a3);
    float2 m1 = make_float2(a0.x + C51*t1.x + C52*t2.x, a0.y + C51*t1.y + C52*t2.y);
    float2 m2 = make_float2(a0.x + C52*t1.x + C51*t2.x, a0.y + C52*t1.y + C51*t2.y);
    float2 u1 = make_float2(S51*t3.x + S52*t4.x, S51*t3.y + S52*t4.y);
    float2 u2 = make_float2(S52*t3.x - S51*t4.x, S52*t3.y - S51*t4.y);
    b0 = make_float2(a0.x + t1.x + t2.x, a0.y + t1.y + t2.y);
    b1 = make_float2(m1.x - dir*u1.y, m1.y + dir*u1.x);
    b4 = make_float2(m1.x + dir*u1.y, m1.y - dir*u1.x);
    b2 = make_float2(m2.x - dir*u2.y, m2.y + dir*u2.x);
    b3 = make_float2(m2.x + dir*u2.y, m2.y - dir*u2.x);
}

// ---------------- per-lane 10-point FFT (natural in/out), DIR=-1 fwd, +1 inv ----------------
template<int DIR>
__device__ __forceinline__ void fft10(float2 v[10]) {
    const float dir = (float)DIR;
    float2 e0,e1,e2,e3,e4, o0,o1,o2,o3,o4;
    fft5<DIR>(v[0], v[2], v[4], v[6], v[8], e0, e1, e2, e3, e4);
    fft5<DIR>(v[1], v[3], v[5], v[7], v[9], o0, o1, o2, o3, o4);
    const float c1 = 0.80901699437494745f, s1 = 0.58778525229247314f;
    const float c2 = 0.30901699437494745f, s2 = 0.95105651629515357f;
    float2 t;
    v[0] = cadd(e0, o0);                       v[5] = csub(e0, o0);
    t = cmul(o1, make_float2( c1, dir*s1));    v[1] = cadd(e1, t); v[6] = csub(e1, t);
    t = cmul(o2, make_float2( c2, dir*s2));    v[2] = cadd(e2, t); v[7] = csub(e2, t);
    t = cmul(o3, make_float2(-c2, dir*s2));    v[3] = cadd(e3, t); v[8] = csub(e3, t);
    t = cmul(o4, make_float2(-c1, dir*s1));    v[4] = cadd(e4, t); v[9] = csub(e4, t);
}

// ---------------- cross-lane 32-pt FFT, forward DIF: natural-lane in, bitrev-lane out ----------------
__device__ __forceinline__ void fft32_dif_fwd(float2 v[10], int lane) {
    #pragma unroll
    for (int m = 16; m >= 1; m >>= 1) {
        int j = lane & (m - 1);
        float sn, cs;
        sincosf(-PI_F * (float)j / (float)m, &sn, &cs);
        float2 w = make_float2(cs, sn);
        bool up = (lane & m) != 0;
        #pragma unroll
        for (int r = 0; r < 10; r++) {
            float ox = __shfl_xor_sync(0xffffffffu, v[r].x, m);
            float oy = __shfl_xor_sync(0xffffffffu, v[r].y, m);
            float2 res;
            if (up) res = cmul(make_float2(ox - v[r].x, oy - v[r].y), w);
            else    res = make_float2(v[r].x + ox, v[r].y + oy);
            v[r] = res;
        }
    }
}

// ---------------- cross-lane 32-pt inverse FFT, DIT: bitrev-lane in, natural-lane out ----------------
__device__ __forceinline__ void fft32_dit_inv(float2 v[10], int lane) {
    #pragma unroll
    for (int m = 1; m <= 16; m <<= 1) {
        int j = lane & (m - 1);
        float sn, cs;
        sincosf(PI_F * (float)j / (float)m, &sn, &cs);
        float2 w = make_float2(cs, sn);
        bool up = (lane & m) != 0;
        #pragma unroll
        for (int r = 0; r < 10; r++) {
            float2 t = up ? cmul(v[r], w) : v[r];
            float ox = __shfl_xor_sync(0xffffffffu, t.x, m);
            float oy = __shfl_xor_sync(0xffffffffu, t.y, m);
            v[r] = up ? make_float2(ox - t.x, oy - t.y)
                      : make_float2(t.x + ox, t.y + oy);
        }
    }
}

__device__ __forceinline__ void twiddle320(float2 v[10], int lane, float dirsign) {
    float sn, cs;
    sincosf(dirsign * (TWOPI / 320.f) * (float)lane, &sn, &cs);
    float2 base = make_float2(cs, sn);
    float2 w = base;
    #pragma unroll
    for (int k = 1; k < 10; k++) {
        v[k] = cmul(v[k], w);
        w = cmul(w, base);
    }
}

// full 320-pt forward: input v[j] = x[lane + 32j]; output lane holds X[10*br5(lane)+j]
__device__ __forceinline__ void fft320_fwd(float2 v[10], int lane) {
    fft10<-1>(v);
    twiddle320(v, lane, -1.f);
    fft32_dif_fwd(v, lane);
}
// full 320-pt inverse (unnormalized): input v[j] = X[10*br5(lane)+j]; output v[j] = x[lane + 32j]
__device__ __forceinline__ void fft320_inv(float2 v[10], int lane) {
    fft32_dit_inv(v, lane);
    twiddle320(v, lane, +1.f);
    fft10<+1>(v);
}

// ---------------- block reduction helper (deterministic tree) ----------------
__device__ __forceinline__ float block_reduce_256(float v) {
    __shared__ float red[256];
    red[threadIdx.x] = v;
    __syncthreads();
    #pragma unroll
    for (int s = 128; s > 0; s >>= 1) {
        if (threadIdx.x < s) red[threadIdx.x] += red[threadIdx.x + s];
        __syncthreads();
    }
    return red[0];
}

// ---------------- mask prep: permuted + scaled, done once per call ----------------
__global__ void __launch_bounds__(256) k_maskprep(const int* __restrict__ mask) {
    int e = blockIdx.x * 256 + threadIdx.x;      // [0, B*HW)
    int b = e / HW; int rem = e - b * HW;
    int w_mem = rem / 320; int idx = rem - w_mem * 320;
    int l = idx & 31, j = idx >> 5;
    int hfreq = 10 * br5(l) + j;
    int wfreq = 10 * br5(w_mem & 31) + (w_mem >> 5);
    g_maskP[e] = (float)mask[b * HW + hfreq * 320 + wfreq] * (1.0f / 102400.0f);
}

// ---------------- K1: coil = csm*p ; forward FFT along W (registers only) ----------------
__global__ void __launch_bounds__(256) k_rows_fwd(const float* __restrict__ csm) {
    int warp = threadIdx.x >> 5, lane = threadIdx.x & 31;
    int row = blockIdx.x * 8 + warp;          // bc*320 + h
    int bc = row / 320, h = row - bc * 320;
    int b = bc >> 4;
    const float2* crow = (const float2*)csm + bc * HW + h * WW;
    const float2* prow = g_p + b * HW + h * WW;
    float2 v[10];
    #pragma unroll
    for (int j = 0; j < 10; j++) {
        int idx = lane + 32 * j;
        v[j] = cmul(crow[idx], prow[idx]);
    }
    fft320_fwd(v, lane);
    float2* out = g_k + bc * HW + h * WW;
    #pragma unroll
    for (int j = 0; j < 10; j++) out[lane + 32 * j] = v[j];   // permuted-freq layout
}

// ---------------- K2: column FFT + mask + column IFFT ----------------
__global__ void __launch_bounds__(256) k_cols() {
    __shared__ float sRe[8][324];
    __shared__ float sIm[8][324];
    int bc = blockIdx.x / 40;
    int w0 = (blockIdx.x - bc * 40) * 8;
    int b = bc >> 4;
    float2* base = g_k + bc * HW;

    // coalesced cooperative load of 8 adjacent memory-columns
    for (int idx = threadIdx.x; idx < 320 * 8; idx += 256) {
        int h = idx >> 3, c = idx & 7;
        float2 t = base[h * WW + w0 + c];
        sRe[c][h] = t.x; sIm[c][h] = t.y;
    }
    __syncthreads();

    int warp = threadIdx.x >> 5, lane = threadIdx.x & 31;
    float2 v[10];
    #pragma unroll
    for (int j = 0; j < 10; j++) {
        int h = lane + 32 * j;
        v[j] = make_float2(sRe[warp][h], sIm[warp][h]);
    }
    fft320_fwd(v, lane);

    // mask in permuted layout: coalesced loads
    const float* mrow = g_maskP + b * HW + (w0 + warp) * 320;
    #pragma unroll
    for (int j = 0; j < 10; j++) {
        float m = mrow[lane + 32 * j];
        v[j].x *= m; v[j].y *= m;
    }
    fft320_inv(v, lane);

    #pragma unroll
    for (int j = 0; j < 10; j++) {
        int h = lane + 32 * j;
        sRe[warp][h] = v[j].x; sIm[warp][h] = v[j].y;
    }
    __syncthreads();
    for (int idx = threadIdx.x; idx < 320 * 8; idx += 256) {
        int h = idx >> 3, c = idx & 7;
        base[h * WW + w0 + c] = make_float2(sRe[c][h], sIm[c][h]);
    }
}

// ---------------- K3: inverse row FFT + conj(csm) + coil combine + lam*p + p.Ap partial ----------------
__global__ void __launch_bounds__(256) k_inv_combine(const float* __restrict__ csm,
                                                     const float* __restrict__ lam) {
    __shared__ float2 sAcc[8][320];
    int warp = threadIdx.x >> 5, lane = threadIdx.x & 31;
    int b = blockIdx.x / 320, h = blockIdx.x - b * 320;

    float2 acc[10];
    #pragma unroll
    for (int j = 0; j < 10; j++) acc[j] = make_float2(0.f, 0.f);

    #pragma unroll
    for (int cc = 0; cc < 2; cc++) {
        int bc = b * 16 + warp + 8 * cc;
        const float2* krow = g_k + bc * HW + h * WW;
        float2 v[10];
        #pragma unroll
        for (int j = 0; j < 10; j++) v[j] = krow[lane + 32 * j];
        fft320_inv(v, lane);
        const float2* crow = (const float2*)csm + bc * HW + h * WW;
        #pragma unroll
        for (int j = 0; j < 10; j++) {
            float2 cv = crow[lane + 32 * j];
            float2 t = cmulconj(cv, v[j]);
            acc[j].x += t.x; acc[j].y += t.y;
        }
    }
    #pragma unroll
    for (int j = 0; j < 10; j++) sAcc[warp][lane + 32 * j] = acc[j];
    __syncthreads();

    const float2* prow = g_p + b * HW + h * WW;
    float2* aprow = g_Ap + b * HW + h * WW;
    float l0 = lam[0];
    float dot = 0.f;
    for (int e = threadIdx.x; e < 320; e += 256) {
        float2 s = make_float2(0.f, 0.f);
        #pragma unroll
        for (int w = 0; w < 8; w++) { s.x += sAcc[w][e].x; s.y += sAcc[w][e].y; }
        float2 pv = prow[e];
        float2 ap = make_float2(s.x + l0 * pv.x, s.y + l0 * pv.y);
        aprow[e] = ap;
        dot += pv.x * ap.x + pv.y * ap.y;
    }
    float tot = block_reduce_256(dot);
    if (threadIdx.x == 0) g_part[blockIdx.x] = tot;   // index = b*320 + h
}

// ---------------- alpha = rTr / pAp ----------------
__global__ void __launch_bounds__(256) k_alpha() {
    int b = blockIdx.x;
    float v = 0.f;
    for (int t = threadIdx.x; t < 320; t += 256) v += g_part[b * 320 + t];
    float tot = block_reduce_256(v);
    if (threadIdx.x == 0) g_alpha[b] = g_rTr[b] / tot;
}

// ---------------- x += a p ; r -= a Ap ; partial rTr_new ----------------
__global__ void __launch_bounds__(256) k_update_xr() {
    int b = blockIdx.x / RED_BLKS;
    int idx = (blockIdx.x - b * RED_BLKS) * 256 + threadIdx.x;
    int e = b * HW + idx;
    float a = g_alpha[b];
    float2 pv = g_p[e], ap = g_Ap[e];
    float2 xv = g_x[e];
    xv.x += a * pv.x; xv.y += a * pv.y;
    g_x[e] = xv;
    float2 rv = g_r[e];
    rv.x -= a * ap.x; rv.y -= a * ap.y;
    g_r[e] = rv;
    float rr = rv.x * rv.x + rv.y * rv.y;
    float tot = block_reduce_256(rr);
    if (threadIdx.x == 0) g_part[blockIdx.x] = tot;
}

// ---------------- beta = rTr_new / rTr ----------------
__global__ void __launch_bounds__(256) k_beta() {
    int b = blockIdx.x;
    float v = 0.f;
    for (int t = threadIdx.x; t < RED_BLKS; t += 256) v += g_part[b * RED_BLKS + t];
    float tot = block_reduce_256(v);
    if (threadIdx.x == 0) {
        g_beta[b] = tot / g_rTr[b];
        g_rTr[b] = tot;
    }
}

// ---------------- p = r + beta p ----------------
__global__ void __launch_bounds__(256) k_update_p() {
    int b = blockIdx.x / RED_BLKS;
    int idx = (blockIdx.x - b * RED_BLKS) * 256 + threadIdx.x;
    int e = b * HW + idx;
    float be = g_beta[b];
    float2 rv = g_r[e], pv = g_p[e];
    g_p[e] = make_float2(rv.x + be * pv.x, rv.y + be * pv.y);
}

// ---------------- init: p=r=rhs (complex), x=0, partial rTr ----------------
__global__ void __launch_bounds__(256) k_init(const float* __restrict__ rhs) {
    int b = blockIdx.x / RED_BLKS;
    int idx = (blockIdx.x - b * RED_BLKS) * 256 + threadIdx.x;
    int e = b * HW + idx;
    float re = rhs[(b * 2 + 0) * HW + idx];
    float im = rhs[(b * 2 + 1) * HW + idx];
    float2 v = make_float2(re, im);
    g_p[e] = v;
    g_r[e] = v;
    g_x[e] = make_float2(0.f, 0.f);
    float rr = re * re + im * im;
    float tot = block_reduce_256(rr);
    if (threadIdx.x == 0) g_part[blockIdx.x] = tot;
}

__global__ void __launch_bounds__(256) k_init_red() {
    int b = blockIdx.x;
    float v = 0.f;
    for (int t = threadIdx.x; t < RED_BLKS; t += 256) v += g_part[b * RED_BLKS + t];
    float tot = block_reduce_256(v);
    if (threadIdx.x == 0) g_rTr[b] = tot;
}

// ---------------- output: [B,H,W,2] ----------------
__global__ void __launch_bounds__(256) k_out(float* __restrict__ out) {
    int e = blockIdx.x * 256 + threadIdx.x;   // [0, 819200)
    float2 v = g_x[e];
    out[2 * e]     = v.x;
    out[2 * e + 1] = v.y;
}

// ---------------- launch ----------------
extern "C" void kernel_launch(void* const* d_in, const int* in_sizes, int n_in,
                              void* d_out, int out_size) {
    const float* rhs  = (const float*)d_in[0];
    const float* csm  = (const float*)d_in[1];
    const int*   mask = (const int*)d_in[2];
    const float* lam  = (const float*)d_in[3];
    float* out = (float*)d_out;

    const int EG = BATCH * RED_BLKS;      // 3200
    const int FG = BATCH * NC * HH / 8;   // 5120 (row FFT: 8 lines/block)
    const int CG = BATCH * NC * (WW / 8); // 5120 (col FFT: 8 cols/block)
    const int IG = BATCH * HH;            // 2560 (inv+combine: 1 (b,h) per block)

    k_maskprep<<<EG, 256>>>(mask);
    k_init<<<EG, 256>>>(rhs);
    k_init_red<<<BATCH, 256>>>();

    for (int it = 0; it < NITER; it++) {
        k_rows_fwd<<<FG, 256>>>(csm);
        k_cols<<<CG, 256>>>();
        k_inv_combine<<<IG, 256>>>(csm, lam);
        k_alpha<<<BATCH, 256>>>();
        k_update_xr<<<EG, 256>>>();
        k_beta<<<BATCH, 256>>>();
        k_update_p<<<EG, 256>>>();
    }

    k_out<<<EG, 256>>>(out);
}